// round 13
// baseline (speedup 1.0000x reference)
#include <cuda_runtime.h>
#include <cuda_bf16.h>
#include <cstdint>

// Problem constants
#define BATCH   2
#define SEQ     2048
#define DMODEL  1024
#define HEADS   16
#define DK      64
#define ROWS    (BATCH * SEQ)          // 4096
#define K2      3072                   // split-bf16 concatenated K (3 * 1024)

// ---------------------------------------------------------------------------
// Scratch (device globals: allocation-free, graph-capture safe)
// ---------------------------------------------------------------------------
__device__ float g_v[ROWS * DMODEL];
__device__ __nv_bfloat16 g_asplit[(size_t)ROWS * K2];     // activations, split
__device__ __nv_bfloat16 g_wsplit[(size_t)DMODEL * K2];   // weights, split
// attention operands (pre-split, per-head layouts)
__device__ __nv_bfloat16 g_qs[(size_t)32 * SEQ * 192];    // [bh][s][192]  [hi|lo|hi]
__device__ __nv_bfloat16 g_ks[(size_t)32 * SEQ * 192];    // [bh][s][192]  [hi|hi|lo]
__device__ __nv_bfloat16 g_vth[(size_t)32 * DK * SEQ];    // [bh][d][s]    V^T hi
__device__ __nv_bfloat16 g_vtl[(size_t)32 * DK * SEQ];    // [bh][d][s]    V^T lo

// ---------------------------------------------------------------------------
// PTX helpers (sm_80+ features only: cp.async, ldmatrix, mma.sync)
// ---------------------------------------------------------------------------
__device__ __forceinline__ uint32_t smem_u32(const void* p) {
    uint32_t a;
    asm("{ .reg .u64 t; cvta.to.shared.u64 t, %1; cvt.u32.u64 %0, t; }"
        : "=r"(a) : "l"(p));
    return a;
}
__device__ __forceinline__ void cp16(uint32_t saddr, const void* g) {
    asm volatile("cp.async.cg.shared.global [%0], [%1], 16;"
                 :: "r"(saddr), "l"(g) : "memory");
}
__device__ __forceinline__ void cp_commit() {
    asm volatile("cp.async.commit_group;" ::: "memory");
}
__device__ __forceinline__ void cp_wait0() { asm volatile("cp.async.wait_group 0;" ::: "memory"); }
__device__ __forceinline__ void cp_wait2() { asm volatile("cp.async.wait_group 2;" ::: "memory"); }

__device__ __forceinline__ void ldmx4(uint32_t* r, uint32_t addr) {
    asm volatile("ldmatrix.sync.aligned.m8n8.x4.shared.b16 {%0,%1,%2,%3}, [%4];"
                 : "=r"(r[0]), "=r"(r[1]), "=r"(r[2]), "=r"(r[3]) : "r"(addr));
}
__device__ __forceinline__ void mma16816(float* d, const uint32_t* a, const uint32_t* b) {
    asm volatile(
        "mma.sync.aligned.m16n8k16.row.col.f32.bf16.bf16.f32 "
        "{%0,%1,%2,%3}, {%4,%5,%6,%7}, {%8,%9}, {%0,%1,%2,%3};"
        : "+f"(d[0]), "+f"(d[1]), "+f"(d[2]), "+f"(d[3])
        : "r"(a[0]), "r"(a[1]), "r"(a[2]), "r"(a[3]), "r"(b[0]), "r"(b[1]));
}

// ---------------------------------------------------------------------------
// Split-bf16 conversion for projection GEMMs: fp32 [rows,1024] -> bf16 [rows,3072]
// act pattern: [hi | lo | hi];  wgt pattern: [hi | hi | lo]
// ---------------------------------------------------------------------------
__global__ void split_kernel(const float4* __restrict__ x,
                             __nv_bfloat16* __restrict__ y, int act)
{
    size_t i = (size_t)blockIdx.x * blockDim.x + threadIdx.x;
    size_t r  = i >> 8;
    size_t c  = (i & 255) * 4;
    float4 v = x[i];
    float f[4] = {v.x, v.y, v.z, v.w};
    __nv_bfloat16 h[4], l[4];
#pragma unroll
    for (int j = 0; j < 4; j++) {
        h[j] = __float2bfloat16(f[j]);
        l[j] = __float2bfloat16(f[j] - __bfloat162float(h[j]));
    }
    uint2 hv = *(uint2*)h;
    uint2 lv = *(uint2*)l;
    __nv_bfloat16* row = y + r * K2;
    *(uint2*)&row[c] = hv;
    if (act) {
        *(uint2*)&row[1024 + c] = lv;
        *(uint2*)&row[2048 + c] = hv;
    } else {
        *(uint2*)&row[1024 + c] = hv;
        *(uint2*)&row[2048 + c] = lv;
    }
}

// ---------------------------------------------------------------------------
// V transpose+split: g_v fp32 [4096,1024] -> vth/vtl [bh][64][2048]
// ---------------------------------------------------------------------------
__global__ void vt_split(const float* __restrict__ v,
                         __nv_bfloat16* __restrict__ vh, __nv_bfloat16* __restrict__ vl)
{
    __shared__ float t[64][65];
    const int bh = blockIdx.x;        // 32
    const int st = blockIdx.y;        // 32 s-tiles
    const int b = bh >> 4, h = bh & 15;
    const int tid = threadIdx.x;      // 256
    for (int i = tid; i < 64 * 16; i += 256) {
        int r = i >> 4, c4 = (i & 15) * 4;
        float4 val = *(const float4*)&v[((size_t)(b * SEQ + st * 64 + r)) * 1024 + h * 64 + c4];
        t[r][c4] = val.x; t[r][c4 + 1] = val.y; t[r][c4 + 2] = val.z; t[r][c4 + 3] = val.w;
    }
    __syncthreads();
    for (int i = tid; i < 64 * 32; i += 256) {
        int d = i >> 5, sp = (i & 31) * 2;
        float f0 = t[sp][d], f1 = t[sp + 1][d];
        __nv_bfloat16 h0 = __float2bfloat16(f0), h1 = __float2bfloat16(f1);
        __nv_bfloat162 hp = __nv_bfloat162(h0, h1);
        __nv_bfloat162 lp = __nv_bfloat162(
            __float2bfloat16(f0 - __bfloat162float(h0)),
            __float2bfloat16(f1 - __bfloat162float(h1)));
        size_t off = ((size_t)bh * 64 + d) * SEQ + st * 64 + sp;
        *(__nv_bfloat162*)(vh + off) = hp;
        *(__nv_bfloat162*)(vl + off) = lp;
    }
}

// ---------------------------------------------------------------------------
// mma.sync bf16 NT GEMM: 4-stage cp.async pipeline, 512 threads, 16 warps
// in 2(m) x 8(n), 64x32 warp tiles (R10-validated geometry).
// mode 0: fp32 C row-major.  mode 1: Q split -> S [bh][s][192] hi|lo|hi, x0.125.
// mode 2: K split -> S [bh][s][192] hi|hi|lo.
// ---------------------------------------------------------------------------
#define GM 128
#define GN 256
#define BKE 32
#define CHUNKB 64
#define NCHUNK (K2 / BKE)       // 96
#define GSTG_A 8192
#define GSTG_B 16384
#define GB_OFF (4 * GSTG_A)     // B region starts at 32KB
#define GEMM_SMEM (4 * (GSTG_A + GSTG_B))   // 98304

__global__ __launch_bounds__(512, 1)
void gemm_mma(const __nv_bfloat16* __restrict__ A, const __nv_bfloat16* __restrict__ B,
              float* __restrict__ C, __nv_bfloat16* __restrict__ S, int mode)
{
    extern __shared__ __align__(128) uint8_t dynsm[];
    const uint32_t smbase = smem_u32(dynsm);

    const int tid    = threadIdx.x;
    const int wid    = tid >> 5;
    const int lane   = tid & 31;
    const int warp_m = wid >> 3;          // 0..1  -> m offset *64
    const int warp_n = wid & 7;           // 0..7  -> n offset *32
    const int rowBase = blockIdx.y * GM;
    const int colBase = blockIdx.x * GN;

    float acc[4][4][4];
#pragma unroll
    for (int i = 0; i < 4; i++)
#pragma unroll
        for (int j = 0; j < 4; j++)
#pragma unroll
            for (int t = 0; t < 4; t++) acc[i][j][t] = 0.f;

    const int a_moff = ((lane >> 3) & 1) * 8 + (lane & 7);
    const int a_half = lane >> 4;
    const int b_noff = (lane >> 4) * 8 + (lane & 7);
    const int b_half = (lane >> 3) & 1;
    const int a_key  = (a_moff >> 1) & 3;   // == (m>>1)&3 (row bases mult of 16)
    const int b_key  = (b_noff >> 1) & 3;

    auto load_chunk = [&](int chunk, int stg) {
        const int k0 = chunk * BKE;
        const uint32_t abase = smbase + stg * GSTG_A;
        const uint32_t bbase = smbase + GB_OFF + stg * GSTG_B;
#pragma unroll
        for (int it = 0; it < 3; it++) {
            int u = tid + it * 512;
            if (u < 512) {
                int r = u >> 2, c = u & 3;
                cp16(abase + r * CHUNKB + ((c ^ ((r >> 1) & 3)) * 16),
                     A + (size_t)(rowBase + r) * K2 + k0 + c * 8);
            } else {
                int v2 = u - 512;
                int r = v2 >> 2, c = v2 & 3;
                cp16(bbase + r * CHUNKB + ((c ^ ((r >> 1) & 3)) * 16),
                     B + (size_t)(colBase + r) * K2 + k0 + c * 8);
            }
        }
        cp_commit();
    };

    // Prologue: 3 stages in flight
    load_chunk(0, 0);
    load_chunk(1, 1);
    load_chunk(2, 2);

    for (int i = 0; i < NCHUNK; i++) {
        const int stg = i & 3;
        cp_wait2();                 // chunk i resident
        __syncthreads();            // protects reuse of stage (i+3)&3 == (i-1)&3

        if (i + 3 < NCHUNK) load_chunk(i + 3, (i + 3) & 3);
        else                cp_commit();

        const uint32_t abase = smbase + stg * GSTG_A;
        const uint32_t bbase = smbase + GB_OFF + stg * GSTG_B;
#pragma unroll
        for (int ks = 0; ks < 2; ks++) {
            uint32_t afrag[4][4], bfrag[4][2];
#pragma unroll
            for (int fi = 0; fi < 4; fi++) {
                int m = warp_m * 64 + fi * 16 + a_moff;
                uint32_t addr = abase + m * CHUNKB
                              + (((ks * 2 + a_half) ^ a_key) * 16);
                ldmx4(afrag[fi], addr);
            }
#pragma unroll
            for (int jj = 0; jj < 2; jj++) {
                int n = warp_n * 32 + jj * 16 + b_noff;
                uint32_t addr = bbase + n * CHUNKB
                              + (((ks * 2 + b_half) ^ b_key) * 16);
                uint32_t r[4];
                ldmx4(r, addr);
                bfrag[jj * 2][0]     = r[0];
                bfrag[jj * 2][1]     = r[1];
                bfrag[jj * 2 + 1][0] = r[2];
                bfrag[jj * 2 + 1][1] = r[3];
            }
#pragma unroll
            for (int fi = 0; fi < 4; fi++)
#pragma unroll
                for (int fj = 0; fj < 4; fj++)
                    mma16816(acc[fi][fj], afrag[fi], bfrag[fj]);
        }
    }

    const int erow = (lane >> 2);
    const int ecol = (lane & 3) * 2;

    if (mode == 0) {
#pragma unroll
        for (int fi = 0; fi < 4; fi++) {
#pragma unroll
            for (int fj = 0; fj < 4; fj++) {
                int row = rowBase + warp_m * 64 + fi * 16 + erow;
                int col = colBase + warp_n * 32 + fj * 8 + ecol;
                *(float2*)&C[(size_t)row * DMODEL + col] =
                    make_float2(acc[fi][fj][0], acc[fi][fj][1]);
                *(float2*)&C[(size_t)(row + 8) * DMODEL + col] =
                    make_float2(acc[fi][fj][2], acc[fi][fj][3]);
            }
        }
    } else {
        const float scl = (mode == 1) ? 0.125f : 1.0f;
#pragma unroll
        for (int fi = 0; fi < 4; fi++) {
#pragma unroll
            for (int fj = 0; fj < 4; fj++) {
                int row0 = rowBase + warp_m * 64 + fi * 16 + erow;
                int col  = colBase + warp_n * 32 + fj * 8 + ecol;
                int h = col >> 6, d = col & 63;
#pragma unroll
                for (int t = 0; t < 2; t++) {
                    int row = row0 + t * 8;
                    float f0 = acc[fi][fj][t * 2 + 0] * scl;
                    float f1 = acc[fi][fj][t * 2 + 1] * scl;
                    __nv_bfloat16 h0 = __float2bfloat16(f0);
                    __nv_bfloat16 h1 = __float2bfloat16(f1);
                    __nv_bfloat162 hp = __nv_bfloat162(h0, h1);
                    __nv_bfloat162 lp = __nv_bfloat162(
                        __float2bfloat16(f0 - __bfloat162float(h0)),
                        __float2bfloat16(f1 - __bfloat162float(h1)));
                    int b = row >> 11, s = row & 2047;
                    __nv_bfloat16* dst = S + (((size_t)(b * 16 + h) * SEQ) + s) * 192;
                    *(__nv_bfloat162*)(dst + d) = hp;
                    if (mode == 1) {
                        *(__nv_bfloat162*)(dst + 64 + d)  = lp;
                        *(__nv_bfloat162*)(dst + 128 + d) = hp;
                    } else {
                        *(__nv_bfloat162*)(dst + 64 + d)  = hp;
                        *(__nv_bfloat162*)(dst + 128 + d) = lp;
                    }
                }
            }
        }
    }
}

// ---------------------------------------------------------------------------
// Tensor-core causal flash attention. Epilogue writes split [hi|lo|hi]
// activations for the O-projection directly (no fp32 round trip).
// ---------------------------------------------------------------------------
#define APITCHB 400                   // bytes per smem row
#define TILEB   (64 * APITCHB)        // 25600
#define SQ_OFF  0
#define SK_OFF  TILEB
#define SV_OFF  (2 * TILEB)
#define SP_OFF  (3 * TILEB)
#define SST_OFF (4 * TILEB)           // state floats
#define ATTN_SMEM (SST_OFF + 512 * 4) // 104448

__global__ __launch_bounds__(256, 2)
void attn_mma(const __nv_bfloat16* __restrict__ qs, const __nv_bfloat16* __restrict__ ks,
              const __nv_bfloat16* __restrict__ vth, const __nv_bfloat16* __restrict__ vtl,
              __nv_bfloat16* __restrict__ outs)
{
    extern __shared__ char sm[];
    const uint32_t sb = smem_u32(sm);
    float* st   = (float*)(sm + SST_OFF);
    float* mrow = st;            // [64]
    float* lrow = st + 64;       // [64]
    float* arow = st + 128;      // [64]
    float* mnew = st + 192;      // [64]
    float* pmax = st + 256;      // [2][64]
    float* psum = st + 384;      // [2][64]

    const int tid  = threadIdx.x;
    const int wid  = tid >> 5;
    const int lane = tid & 31;
    const int wm   = wid & 3;          // 16-row strip
    const int wn   = wid >> 2;         // 32-col strip
    const int qb   = blockIdx.x;
    const int bh   = blockIdx.y;

    const __nv_bfloat16* qsrc = qs  + ((size_t)bh * SEQ + qb * 64) * 192;
    const __nv_bfloat16* ksrc = ks  + (size_t)bh * SEQ * 192;
    const __nv_bfloat16* vhs  = vth + (size_t)bh * 64 * SEQ;
    const __nv_bfloat16* vls  = vtl + (size_t)bh * 64 * SEQ;

    // Q' load (once)
    for (int u = tid; u < 1536; u += 256) {
        int r = u / 24, c = u % 24;
        cp16(sb + SQ_OFF + r * APITCHB + c * 16, qsrc + (size_t)r * 192 + c * 8);
    }
    cp_commit();

    if (tid < 64) { mrow[tid] = -1e30f; lrow[tid] = 0.f; }

    float acco[4][4];
#pragma unroll
    for (int j = 0; j < 4; j++)
#pragma unroll
        for (int t = 0; t < 4; t++) acco[j][t] = 0.f;

    const int a_moff = ((lane >> 3) & 1) * 8 + (lane & 7);
    const int a_half = lane >> 4;
    const int b_noff = (lane >> 4) * 8 + (lane & 7);
    const int b_half = (lane >> 3) & 1;
    const int erow   = lane >> 2;
    const int ecol   = (lane & 3) * 2;
    const int r0 = wm * 16 + erow, r1 = r0 + 8;

    for (int kb = 0; kb <= qb; kb++) {
        // K' tile
        for (int u = tid; u < 1536; u += 256) {
            int r = u / 24, c = u % 24;
            cp16(sb + SK_OFF + r * APITCHB + c * 16,
                 ksrc + ((size_t)(kb * 64 + r)) * 192 + c * 8);
        }
        // VT' tile: cols [0:16) chunks from hi (dup), [16:24) from lo
        for (int u = tid; u < 1536; u += 256) {
            int r = u / 24, c = u % 24;
            const __nv_bfloat16* src = (c < 16)
                ? (vhs + (size_t)r * SEQ + kb * 64 + (c & 7) * 8)
                : (vls + (size_t)r * SEQ + kb * 64 + (c - 16) * 8);
            cp16(sb + SV_OFF + r * APITCHB + c * 16, src);
        }
        cp_commit();
        cp_wait0();
        __syncthreads();

        // ---- S = Q' K'^T  (12 k-steps) ----
        float accs[4][4];
#pragma unroll
        for (int j = 0; j < 4; j++)
#pragma unroll
            for (int t = 0; t < 4; t++) accs[j][t] = 0.f;

#pragma unroll
        for (int ks_ = 0; ks_ < 12; ks_++) {
            uint32_t af[4], bf[4][2];
            ldmx4(af, sb + SQ_OFF + (wm * 16 + a_moff) * APITCHB + ks_ * 32 + a_half * 16);
#pragma unroll
            for (int jj = 0; jj < 2; jj++) {
                uint32_t r[4];
                ldmx4(r, sb + SK_OFF + (wn * 32 + jj * 16 + b_noff) * APITCHB
                         + ks_ * 32 + b_half * 16);
                bf[jj * 2][0] = r[0]; bf[jj * 2][1] = r[1];
                bf[jj * 2 + 1][0] = r[2]; bf[jj * 2 + 1][1] = r[3];
            }
#pragma unroll
            for (int fj = 0; fj < 4; fj++) mma16816(accs[fj], af, bf[fj]);
        }

        // causal mask (diagonal tile)
        if (kb == qb) {
#pragma unroll
            for (int fj = 0; fj < 4; fj++) {
                int gc = wn * 32 + fj * 8 + ecol;
                if (gc     > r0) accs[fj][0] = -1e30f;
                if (gc + 1 > r0) accs[fj][1] = -1e30f;
                if (gc     > r1) accs[fj][2] = -1e30f;
                if (gc + 1 > r1) accs[fj][3] = -1e30f;
            }
        }

        // ---- row maxes ----
        float lm0 = -1e30f, lm1 = -1e30f;
#pragma unroll
        for (int fj = 0; fj < 4; fj++) {
            lm0 = fmaxf(lm0, fmaxf(accs[fj][0], accs[fj][1]));
            lm1 = fmaxf(lm1, fmaxf(accs[fj][2], accs[fj][3]));
        }
        lm0 = fmaxf(lm0, __shfl_xor_sync(0xFFFFFFFF, lm0, 1));
        lm0 = fmaxf(lm0, __shfl_xor_sync(0xFFFFFFFF, lm0, 2));
        lm1 = fmaxf(lm1, __shfl_xor_sync(0xFFFFFFFF, lm1, 1));
        lm1 = fmaxf(lm1, __shfl_xor_sync(0xFFFFFFFF, lm1, 2));
        if ((lane & 3) == 0) {
            pmax[wn * 64 + r0] = lm0;
            pmax[wn * 64 + r1] = lm1;
        }
        __syncthreads();

        if (tid < 64) {
            float mo = mrow[tid];
            float mn = fmaxf(mo, fmaxf(pmax[tid], pmax[64 + tid]));
            mnew[tid] = mn;
            arow[tid] = __expf(mo - mn);
            mrow[tid] = mn;
        }
        __syncthreads();

        // ---- exp, write P' (hi|lo|hi), partial sums, rescale O ----
        const float mn0 = mnew[r0], mn1 = mnew[r1];
        const float al0 = arow[r0], al1 = arow[r1];
        float s0 = 0.f, s1 = 0.f;
#pragma unroll
        for (int fj = 0; fj < 4; fj++) {
            int kc = wn * 32 + fj * 8 + ecol;
            float p00 = __expf(accs[fj][0] - mn0);
            float p01 = __expf(accs[fj][1] - mn0);
            float p10 = __expf(accs[fj][2] - mn1);
            float p11 = __expf(accs[fj][3] - mn1);
            s0 += p00 + p01;
            s1 += p10 + p11;
            __nv_bfloat16 h00 = __float2bfloat16(p00), h01 = __float2bfloat16(p01);
            __nv_bfloat16 h10 = __float2bfloat16(p10), h11 = __float2bfloat16(p11);
            __nv_bfloat162 hp0 = __nv_bfloat162(h00, h01);
            __nv_bfloat162 hp1 = __nv_bfloat162(h10, h11);
            __nv_bfloat162 lp0 = __nv_bfloat162(
                __float2bfloat16(p00 - __bfloat162float(h00)),
                __float2bfloat16(p01 - __bfloat162float(h01)));
            __nv_bfloat162 lp1 = __nv_bfloat162(
                __float2bfloat16(p10 - __bfloat162float(h10)),
                __float2bfloat16(p11 - __bfloat162float(h11)));
            char* pr0 = sm + SP_OFF + r0 * APITCHB;
            char* pr1 = sm + SP_OFF + r1 * APITCHB;
            *(__nv_bfloat162*)(pr0 + kc * 2)       = hp0;
            *(__nv_bfloat162*)(pr0 + 128 + kc * 2) = lp0;
            *(__nv_bfloat162*)(pr0 + 256 + kc * 2) = hp0;
            *(__nv_bfloat162*)(pr1 + kc * 2)       = hp1;
            *(__nv_bfloat162*)(pr1 + 128 + kc * 2) = lp1;
            *(__nv_bfloat162*)(pr1 + 256 + kc * 2) = hp1;
        }
        s0 += __shfl_xor_sync(0xFFFFFFFF, s0, 1);
        s0 += __shfl_xor_sync(0xFFFFFFFF, s0, 2);
        s1 += __shfl_xor_sync(0xFFFFFFFF, s1, 1);
        s1 += __shfl_xor_sync(0xFFFFFFFF, s1, 2);
        if ((lane & 3) == 0) {
            psum[wn * 64 + r0] = s0;
            psum[wn * 64 + r1] = s1;
        }
#pragma unroll
        for (int fj = 0; fj < 4; fj++) {
            acco[fj][0] *= al0; acco[fj][1] *= al0;
            acco[fj][2] *= al1; acco[fj][3] *= al1;
        }
        __syncthreads();
        if (tid < 64)
            lrow[tid] = lrow[tid] * arow[tid] + psum[tid] + psum[64 + tid];

        // ---- O += P' VT'^T  (12 k-steps) ----
#pragma unroll
        for (int ks_ = 0; ks_ < 12; ks_++) {
            uint32_t af[4], bf[4][2];
            ldmx4(af, sb + SP_OFF + (wm * 16 + a_moff) * APITCHB + ks_ * 32 + a_half * 16);
#pragma unroll
            for (int jj = 0; jj < 2; jj++) {
                uint32_t r[4];
                ldmx4(r, sb + SV_OFF + (wn * 32 + jj * 16 + b_noff) * APITCHB
                         + ks_ * 32 + b_half * 16);
                bf[jj * 2][0] = r[0]; bf[jj * 2][1] = r[1];
                bf[jj * 2 + 1][0] = r[2]; bf[jj * 2 + 1][1] = r[3];
            }
#pragma unroll
            for (int fj = 0; fj < 4; fj++) mma16816(acco[fj], af, bf[fj]);
        }
        __syncthreads();
    }

    // ---- finalize: O /= l, write split [hi|lo|hi] into g_asplit ----
    const int b = bh >> 4, h = bh & 15;
    const float il0 = 1.f / lrow[r0];
    const float il1 = 1.f / lrow[r1];
    __nv_bfloat16* drow0 = outs + (size_t)(b * SEQ + qb * 64 + r0) * K2;
    __nv_bfloat16* drow1 = outs + (size_t)(b * SEQ + qb * 64 + r1) * K2;
#pragma unroll
    for (int fj = 0; fj < 4; fj++) {
        int col = h * 64 + wn * 32 + fj * 8 + ecol;
        float f00 = acco[fj][0] * il0, f01 = acco[fj][1] * il0;
        float f10 = acco[fj][2] * il1, f11 = acco[fj][3] * il1;
        __nv_bfloat16 h00 = __float2bfloat16(f00), h01 = __float2bfloat16(f01);
        __nv_bfloat16 h10 = __float2bfloat16(f10), h11 = __float2bfloat16(f11);
        __nv_bfloat162 hp0 = __nv_bfloat162(h00, h01);
        __nv_bfloat162 hp1 = __nv_bfloat162(h10, h11);
        __nv_bfloat162 lp0 = __nv_bfloat162(
            __float2bfloat16(f00 - __bfloat162float(h00)),
            __float2bfloat16(f01 - __bfloat162float(h01)));
        __nv_bfloat162 lp1 = __nv_bfloat162(
            __float2bfloat16(f10 - __bfloat162float(h10)),
            __float2bfloat16(f11 - __bfloat162float(h11)));
        *(__nv_bfloat162*)(drow0 + col)        = hp0;
        *(__nv_bfloat162*)(drow0 + 1024 + col) = lp0;
        *(__nv_bfloat162*)(drow0 + 2048 + col) = hp0;
        *(__nv_bfloat162*)(drow1 + col)        = hp1;
        *(__nv_bfloat162*)(drow1 + 1024 + col) = lp1;
        *(__nv_bfloat162*)(drow1 + 2048 + col) = hp1;
    }
}

// ---------------------------------------------------------------------------
// Launch
// ---------------------------------------------------------------------------
extern "C" void kernel_launch(void* const* d_in, const int* in_sizes, int n_in,
                              void* d_out, int out_size)
{
    const float* Q   = (const float*)d_in[0];
    const float* K   = (const float*)d_in[1];
    const float* V   = (const float*)d_in[2];
    const float* W_Q = (const float*)d_in[4];
    const float* W_K = (const float*)d_in[5];
    const float* W_V = (const float*)d_in[6];
    const float* W_O = (const float*)d_in[7];
    float* out = (float*)d_out;

    float *pv;
    __nv_bfloat16 *pas, *pws, *pqs, *pks, *pvh, *pvl;
    cudaGetSymbolAddress((void**)&pv, g_v);
    cudaGetSymbolAddress((void**)&pas, g_asplit);
    cudaGetSymbolAddress((void**)&pws, g_wsplit);
    cudaGetSymbolAddress((void**)&pqs, g_qs);
    cudaGetSymbolAddress((void**)&pks, g_ks);
    cudaGetSymbolAddress((void**)&pvh, g_vth);
    cudaGetSymbolAddress((void**)&pvl, g_vtl);

    cudaFuncSetAttribute(gemm_mma,
                         cudaFuncAttributeMaxDynamicSharedMemorySize, GEMM_SMEM);
    cudaFuncSetAttribute(attn_mma,
                         cudaFuncAttributeMaxDynamicSharedMemorySize, ATTN_SMEM);

    const int actBlocks = ROWS * DMODEL / 4 / 256;     // 4096
    const int wgtBlocks = DMODEL * DMODEL / 4 / 256;   // 1024
    dim3 gg(DMODEL / GN, ROWS / GM);                   // (4, 32)

    // Q projection -> split attention layout directly
    split_kernel<<<actBlocks, 256>>>((const float4*)Q, pas, 1);
    split_kernel<<<wgtBlocks, 256>>>((const float4*)W_Q, pws, 0);
    gemm_mma<<<gg, 512, GEMM_SMEM>>>(pas, pws, nullptr, pqs, 1);
    // K projection -> split attention layout directly
    split_kernel<<<actBlocks, 256>>>((const float4*)K, pas, 1);
    split_kernel<<<wgtBlocks, 256>>>((const float4*)W_K, pws, 0);
    gemm_mma<<<gg, 512, GEMM_SMEM>>>(pas, pws, nullptr, pks, 2);
    // V projection -> fp32, then transpose+split
    split_kernel<<<actBlocks, 256>>>((const float4*)V, pas, 1);
    split_kernel<<<wgtBlocks, 256>>>((const float4*)W_V, pws, 0);
    gemm_mma<<<gg, 512, GEMM_SMEM>>>(pas, pws, pv, nullptr, 0);
    vt_split<<<dim3(32, 32), 256>>>(pv, pvh, pvl);

    // Tensor-core attention -> writes O-proj activations (split) directly
    attn_mma<<<dim3(SEQ / 64, BATCH * HEADS), 256, ATTN_SMEM>>>(pqs, pks, pvh, pvl, pas);

    // Output projection
    split_kernel<<<wgtBlocks, 256>>>((const float4*)W_O, pws, 0);
    gemm_mma<<<gg, 512, GEMM_SMEM>>>(pas, pws, out, nullptr, 0);
}

// round 15
// speedup vs baseline: 1.0366x; 1.0366x over previous
#include <cuda_runtime.h>
#include <cuda_bf16.h>
#include <cstdint>

// Problem constants
#define BATCH   2
#define SEQ     2048
#define DMODEL  1024
#define HEADS   16
#define DK      64
#define ROWS    (BATCH * SEQ)          // 4096
#define K2      3072                   // split-bf16 concatenated K (3 * 1024)

// ---------------------------------------------------------------------------
// Scratch (device globals: allocation-free, graph-capture safe)
// ---------------------------------------------------------------------------
__device__ float g_v[ROWS * DMODEL];
__device__ __nv_bfloat16 g_asplit[(size_t)ROWS * K2];     // activations, split
__device__ __nv_bfloat16 g_wsplit[(size_t)DMODEL * K2];   // weights, split
// attention operands (pre-split, per-head layouts)
__device__ __nv_bfloat16 g_qs[(size_t)32 * SEQ * 192];    // [bh][s][192]  [hi|lo|hi]
__device__ __nv_bfloat16 g_ks[(size_t)32 * SEQ * 192];    // [bh][s][192]  [hi|hi|lo]
__device__ __nv_bfloat16 g_vth[(size_t)32 * DK * SEQ];    // [bh][d][s]    V^T hi
__device__ __nv_bfloat16 g_vtl[(size_t)32 * DK * SEQ];    // [bh][d][s]    V^T lo

// ---------------------------------------------------------------------------
// PTX helpers (sm_80+ features only: cp.async, ldmatrix, mma.sync)
// ---------------------------------------------------------------------------
__device__ __forceinline__ uint32_t smem_u32(const void* p) {
    uint32_t a;
    asm("{ .reg .u64 t; cvta.to.shared.u64 t, %1; cvt.u32.u64 %0, t; }"
        : "=r"(a) : "l"(p));
    return a;
}
__device__ __forceinline__ void cp16(uint32_t saddr, const void* g) {
    asm volatile("cp.async.cg.shared.global [%0], [%1], 16;"
                 :: "r"(saddr), "l"(g) : "memory");
}
__device__ __forceinline__ void cp_commit() {
    asm volatile("cp.async.commit_group;" ::: "memory");
}
__device__ __forceinline__ void cp_wait0() { asm volatile("cp.async.wait_group 0;" ::: "memory"); }
__device__ __forceinline__ void cp_wait2() { asm volatile("cp.async.wait_group 2;" ::: "memory"); }

__device__ __forceinline__ void ldmx4(uint32_t* r, uint32_t addr) {
    asm volatile("ldmatrix.sync.aligned.m8n8.x4.shared.b16 {%0,%1,%2,%3}, [%4];"
                 : "=r"(r[0]), "=r"(r[1]), "=r"(r[2]), "=r"(r[3]) : "r"(addr));
}
__device__ __forceinline__ void mma16816(float* d, const uint32_t* a, const uint32_t* b) {
    asm volatile(
        "mma.sync.aligned.m16n8k16.row.col.f32.bf16.bf16.f32 "
        "{%0,%1,%2,%3}, {%4,%5,%6,%7}, {%8,%9}, {%0,%1,%2,%3};"
        : "+f"(d[0]), "+f"(d[1]), "+f"(d[2]), "+f"(d[3])
        : "r"(a[0]), "r"(a[1]), "r"(a[2]), "r"(a[3]), "r"(b[0]), "r"(b[1]));
}

// ---------------------------------------------------------------------------
// Split-bf16 conversion for projection GEMMs: fp32 [rows,1024] -> bf16 [rows,3072]
// act pattern: [hi | lo | hi];  wgt pattern: [hi | hi | lo]
// ---------------------------------------------------------------------------
__global__ void split_kernel(const float4* __restrict__ x,
                             __nv_bfloat16* __restrict__ y, int act)
{
    size_t i = (size_t)blockIdx.x * blockDim.x + threadIdx.x;
    size_t r  = i >> 8;
    size_t c  = (i & 255) * 4;
    float4 v = x[i];
    float f[4] = {v.x, v.y, v.z, v.w};
    __nv_bfloat16 h[4], l[4];
#pragma unroll
    for (int j = 0; j < 4; j++) {
        h[j] = __float2bfloat16(f[j]);
        l[j] = __float2bfloat16(f[j] - __bfloat162float(h[j]));
    }
    uint2 hv = *(uint2*)h;
    uint2 lv = *(uint2*)l;
    __nv_bfloat16* row = y + r * K2;
    *(uint2*)&row[c] = hv;
    if (act) {
        *(uint2*)&row[1024 + c] = lv;
        *(uint2*)&row[2048 + c] = hv;
    } else {
        *(uint2*)&row[1024 + c] = hv;
        *(uint2*)&row[2048 + c] = lv;
    }
}

// ---------------------------------------------------------------------------
// V transpose+split: g_v fp32 [4096,1024] -> vth/vtl [bh][64][2048]
// ---------------------------------------------------------------------------
__global__ void vt_split(const float* __restrict__ v,
                         __nv_bfloat16* __restrict__ vh, __nv_bfloat16* __restrict__ vl)
{
    __shared__ float t[64][65];
    const int bh = blockIdx.x;        // 32
    const int st = blockIdx.y;        // 32 s-tiles
    const int b = bh >> 4, h = bh & 15;
    const int tid = threadIdx.x;      // 256
    for (int i = tid; i < 64 * 16; i += 256) {
        int r = i >> 4, c4 = (i & 15) * 4;
        float4 val = *(const float4*)&v[((size_t)(b * SEQ + st * 64 + r)) * 1024 + h * 64 + c4];
        t[r][c4] = val.x; t[r][c4 + 1] = val.y; t[r][c4 + 2] = val.z; t[r][c4 + 3] = val.w;
    }
    __syncthreads();
    for (int i = tid; i < 64 * 32; i += 256) {
        int d = i >> 5, sp = (i & 31) * 2;
        float f0 = t[sp][d], f1 = t[sp + 1][d];
        __nv_bfloat16 h0 = __float2bfloat16(f0), h1 = __float2bfloat16(f1);
        __nv_bfloat162 hp = __nv_bfloat162(h0, h1);
        __nv_bfloat162 lp = __nv_bfloat162(
            __float2bfloat16(f0 - __bfloat162float(h0)),
            __float2bfloat16(f1 - __bfloat162float(h1)));
        size_t off = ((size_t)bh * 64 + d) * SEQ + st * 64 + sp;
        *(__nv_bfloat162*)(vh + off) = hp;
        *(__nv_bfloat162*)(vl + off) = lp;
    }
}

// ---------------------------------------------------------------------------
// mma.sync bf16 NT GEMM: 4-stage cp.async pipeline, 512 threads, 16 warps
// in 2(m) x 8(n), 64x32 warp tiles.
// mode 0: fp32 C row-major.
// mode 1/2: split attention layout via SMEM-STAGED COALESCED epilogue:
//   stage one head's [128][192] split tile in smem, then stream out as one
//   contiguous 48KB block per (CTA, head).
// ---------------------------------------------------------------------------
#define GM 128
#define GN 256
#define BKE 32
#define CHUNKB 64
#define NCHUNK (K2 / BKE)       // 96
#define GSTG_A 8192
#define GSTG_B 16384
#define GB_OFF (4 * GSTG_A)     // B region starts at 32KB
#define GEMM_SMEM (4 * (GSTG_A + GSTG_B))   // 98304
#define EPITCH 400              // staging pitch (bytes) per row

__global__ __launch_bounds__(512, 1)
void gemm_mma(const __nv_bfloat16* __restrict__ A, const __nv_bfloat16* __restrict__ B,
              float* __restrict__ C, __nv_bfloat16* __restrict__ S, int mode)
{
    extern __shared__ __align__(128) uint8_t dynsm[];
    const uint32_t smbase = smem_u32(dynsm);

    const int tid    = threadIdx.x;
    const int wid    = tid >> 5;
    const int lane   = tid & 31;
    const int warp_m = wid >> 3;          // 0..1  -> m offset *64
    const int warp_n = wid & 7;           // 0..7  -> n offset *32
    const int rowBase = blockIdx.y * GM;
    const int colBase = blockIdx.x * GN;

    float acc[4][4][4];
#pragma unroll
    for (int i = 0; i < 4; i++)
#pragma unroll
        for (int j = 0; j < 4; j++)
#pragma unroll
            for (int t = 0; t < 4; t++) acc[i][j][t] = 0.f;

    const int a_moff = ((lane >> 3) & 1) * 8 + (lane & 7);
    const int a_half = lane >> 4;
    const int b_noff = (lane >> 4) * 8 + (lane & 7);
    const int b_half = (lane >> 3) & 1;
    const int a_key  = (a_moff >> 1) & 3;
    const int b_key  = (b_noff >> 1) & 3;

    auto load_chunk = [&](int chunk, int stg) {
        const int k0 = chunk * BKE;
        const uint32_t abase = smbase + stg * GSTG_A;
        const uint32_t bbase = smbase + GB_OFF + stg * GSTG_B;
#pragma unroll
        for (int it = 0; it < 3; it++) {
            int u = tid + it * 512;
            if (u < 512) {
                int r = u >> 2, c = u & 3;
                cp16(abase + r * CHUNKB + ((c ^ ((r >> 1) & 3)) * 16),
                     A + (size_t)(rowBase + r) * K2 + k0 + c * 8);
            } else {
                int v2 = u - 512;
                int r = v2 >> 2, c = v2 & 3;
                cp16(bbase + r * CHUNKB + ((c ^ ((r >> 1) & 3)) * 16),
                     B + (size_t)(colBase + r) * K2 + k0 + c * 8);
            }
        }
        cp_commit();
    };

    load_chunk(0, 0);
    load_chunk(1, 1);
    load_chunk(2, 2);

    for (int i = 0; i < NCHUNK; i++) {
        const int stg = i & 3;
        cp_wait2();
        __syncthreads();

        if (i + 3 < NCHUNK) load_chunk(i + 3, (i + 3) & 3);
        else                cp_commit();

        const uint32_t abase = smbase + stg * GSTG_A;
        const uint32_t bbase = smbase + GB_OFF + stg * GSTG_B;
#pragma unroll
        for (int ks = 0; ks < 2; ks++) {
            uint32_t afrag[4][4], bfrag[4][2];
#pragma unroll
            for (int fi = 0; fi < 4; fi++) {
                int m = warp_m * 64 + fi * 16 + a_moff;
                uint32_t addr = abase + m * CHUNKB
                              + (((ks * 2 + a_half) ^ a_key) * 16);
                ldmx4(afrag[fi], addr);
            }
#pragma unroll
            for (int jj = 0; jj < 2; jj++) {
                int n = warp_n * 32 + jj * 16 + b_noff;
                uint32_t addr = bbase + n * CHUNKB
                              + (((ks * 2 + b_half) ^ b_key) * 16);
                uint32_t r[4];
                ldmx4(r, addr);
                bfrag[jj * 2][0]     = r[0];
                bfrag[jj * 2][1]     = r[1];
                bfrag[jj * 2 + 1][0] = r[2];
                bfrag[jj * 2 + 1][1] = r[3];
            }
#pragma unroll
            for (int fi = 0; fi < 4; fi++)
#pragma unroll
                for (int fj = 0; fj < 4; fj++)
                    mma16816(acc[fi][fj], afrag[fi], bfrag[fj]);
        }
    }

    const int erow = (lane >> 2);
    const int ecol = (lane & 3) * 2;

    if (mode == 0) {
#pragma unroll
        for (int fi = 0; fi < 4; fi++) {
#pragma unroll
            for (int fj = 0; fj < 4; fj++) {
                int row = rowBase + warp_m * 64 + fi * 16 + erow;
                int col = colBase + warp_n * 32 + fj * 8 + ecol;
                *(float2*)&C[(size_t)row * DMODEL + col] =
                    make_float2(acc[fi][fj][0], acc[fi][fj][1]);
                *(float2*)&C[(size_t)(row + 8) * DMODEL + col] =
                    make_float2(acc[fi][fj][2], acc[fi][fj][3]);
            }
        }
    } else {
        // ---- staged coalesced split epilogue ----
        const float scl = (mode == 1) ? 0.125f : 1.0f;
        const int b  = rowBase >> 11;          // 128-row tiles never cross batch
        const int s0 = rowBase & 2047;
        __syncthreads();                       // pipeline smem now dead

        for (int hh = 0; hh < 4; hh++) {
            // stage: warps covering this head's 64 cols (warp_n in {2hh, 2hh+1})
            if ((warp_n >> 1) == hh) {
#pragma unroll
                for (int fi = 0; fi < 4; fi++) {
#pragma unroll
                    for (int fj = 0; fj < 4; fj++) {
                        int col = warp_n * 32 + fj * 8 + ecol;
                        int d   = col & 63;
                        int row0 = warp_m * 64 + fi * 16 + erow;   // local 0..127
#pragma unroll
                        for (int t = 0; t < 2; t++) {
                            int row = row0 + t * 8;
                            float f0 = acc[fi][fj][t * 2 + 0] * scl;
                            float f1 = acc[fi][fj][t * 2 + 1] * scl;
                            __nv_bfloat16 h0 = __float2bfloat16(f0);
                            __nv_bfloat16 h1 = __float2bfloat16(f1);
                            __nv_bfloat162 hp = __nv_bfloat162(h0, h1);
                            __nv_bfloat162 lp = __nv_bfloat162(
                                __float2bfloat16(f0 - __bfloat162float(h0)),
                                __float2bfloat16(f1 - __bfloat162float(h1)));
                            uint8_t* rb = dynsm + row * EPITCH + d * 2;
                            if (mode == 1) {
                                *(__nv_bfloat162*)(rb)       = hp;
                                *(__nv_bfloat162*)(rb + 128) = lp;
                                *(__nv_bfloat162*)(rb + 256) = hp;
                            } else {
                                *(__nv_bfloat162*)(rb)       = hp;
                                *(__nv_bfloat162*)(rb + 128) = hp;
                                *(__nv_bfloat162*)(rb + 256) = lp;
                            }
                        }
                    }
                }
            }
            __syncthreads();
            // write out: contiguous 128 rows x 384B per (CTA, head)
            {
                const int ghead = blockIdx.x * 4 + hh;
                __nv_bfloat16* dstbase =
                    S + (((size_t)(b * 16 + ghead) * SEQ) + s0) * 192;
#pragma unroll
                for (int it = 0; it < 6; it++) {
                    int u = tid + it * 512;        // 0..3071
                    int row = u / 24, c = u % 24;
                    uint4 v = *(uint4*)(dynsm + row * EPITCH + c * 16);
                    *(uint4*)(dstbase + (size_t)row * 192 + c * 8) = v;
                }
            }
            __syncthreads();
        }
    }
}

// ---------------------------------------------------------------------------
// Tensor-core causal flash attention. Descending-qb schedule (heavy CTAs
// first); staged coalesced split epilogue through the SP smem region.
// ---------------------------------------------------------------------------
#define APITCHB 400                   // bytes per smem row
#define TILEB   (64 * APITCHB)        // 25600
#define SQ_OFF  0
#define SK_OFF  TILEB
#define SV_OFF  (2 * TILEB)
#define SP_OFF  (3 * TILEB)
#define SST_OFF (4 * TILEB)           // state floats
#define ATTN_SMEM (SST_OFF + 512 * 4) // 104448

__global__ __launch_bounds__(256, 2)
void attn_mma(const __nv_bfloat16* __restrict__ qs, const __nv_bfloat16* __restrict__ ks,
              const __nv_bfloat16* __restrict__ vth, const __nv_bfloat16* __restrict__ vtl,
              __nv_bfloat16* __restrict__ outs)
{
    extern __shared__ char sm[];
    const uint32_t sb = smem_u32(sm);
    float* st   = (float*)(sm + SST_OFF);
    float* mrow = st;            // [64]
    float* lrow = st + 64;       // [64]
    float* arow = st + 128;      // [64]
    float* mnew = st + 192;      // [64]
    float* pmax = st + 256;      // [2][64]
    float* psum = st + 384;      // [2][64]

    const int tid  = threadIdx.x;
    const int wid  = tid >> 5;
    const int lane = tid & 31;
    const int wm   = wid & 3;          // 16-row strip
    const int wn   = wid >> 2;         // 32-col strip
    const int qb   = gridDim.x - 1 - blockIdx.x;   // heavy tiles first
    const int bh   = blockIdx.y;

    const __nv_bfloat16* qsrc = qs  + ((size_t)bh * SEQ + qb * 64) * 192;
    const __nv_bfloat16* ksrc = ks  + (size_t)bh * SEQ * 192;
    const __nv_bfloat16* vhs  = vth + (size_t)bh * 64 * SEQ;
    const __nv_bfloat16* vls  = vtl + (size_t)bh * 64 * SEQ;

    // Q' load (once)
    for (int u = tid; u < 1536; u += 256) {
        int r = u / 24, c = u % 24;
        cp16(sb + SQ_OFF + r * APITCHB + c * 16, qsrc + (size_t)r * 192 + c * 8);
    }
    cp_commit();

    if (tid < 64) { mrow[tid] = -1e30f; lrow[tid] = 0.f; }

    float acco[4][4];
#pragma unroll
    for (int j = 0; j < 4; j++)
#pragma unroll
        for (int t = 0; t < 4; t++) acco[j][t] = 0.f;

    const int a_moff = ((lane >> 3) & 1) * 8 + (lane & 7);
    const int a_half = lane >> 4;
    const int b_noff = (lane >> 4) * 8 + (lane & 7);
    const int b_half = (lane >> 3) & 1;
    const int erow   = lane >> 2;
    const int ecol   = (lane & 3) * 2;
    const int r0 = wm * 16 + erow, r1 = r0 + 8;

    for (int kb = 0; kb <= qb; kb++) {
        // K' tile
        for (int u = tid; u < 1536; u += 256) {
            int r = u / 24, c = u % 24;
            cp16(sb + SK_OFF + r * APITCHB + c * 16,
                 ksrc + ((size_t)(kb * 64 + r)) * 192 + c * 8);
        }
        // VT' tile: cols [0:16) chunks from hi (dup), [16:24) from lo
        for (int u = tid; u < 1536; u += 256) {
            int r = u / 24, c = u % 24;
            const __nv_bfloat16* src = (c < 16)
                ? (vhs + (size_t)r * SEQ + kb * 64 + (c & 7) * 8)
                : (vls + (size_t)r * SEQ + kb * 64 + (c - 16) * 8);
            cp16(sb + SV_OFF + r * APITCHB + c * 16, src);
        }
        cp_commit();
        cp_wait0();
        __syncthreads();

        // ---- S = Q' K'^T  (12 k-steps) ----
        float accs[4][4];
#pragma unroll
        for (int j = 0; j < 4; j++)
#pragma unroll
            for (int t = 0; t < 4; t++) accs[j][t] = 0.f;

#pragma unroll
        for (int ks_ = 0; ks_ < 12; ks_++) {
            uint32_t af[4], bf[4][2];
            ldmx4(af, sb + SQ_OFF + (wm * 16 + a_moff) * APITCHB + ks_ * 32 + a_half * 16);
#pragma unroll
            for (int jj = 0; jj < 2; jj++) {
                uint32_t r[4];
                ldmx4(r, sb + SK_OFF + (wn * 32 + jj * 16 + b_noff) * APITCHB
                         + ks_ * 32 + b_half * 16);
                bf[jj * 2][0] = r[0]; bf[jj * 2][1] = r[1];
                bf[jj * 2 + 1][0] = r[2]; bf[jj * 2 + 1][1] = r[3];
            }
#pragma unroll
            for (int fj = 0; fj < 4; fj++) mma16816(accs[fj], af, bf[fj]);
        }

        // causal mask (diagonal tile)
        if (kb == qb) {
#pragma unroll
            for (int fj = 0; fj < 4; fj++) {
                int gc = wn * 32 + fj * 8 + ecol;
                if (gc     > r0) accs[fj][0] = -1e30f;
                if (gc + 1 > r0) accs[fj][1] = -1e30f;
                if (gc     > r1) accs[fj][2] = -1e30f;
                if (gc + 1 > r1) accs[fj][3] = -1e30f;
            }
        }

        // ---- row maxes ----
        float lm0 = -1e30f, lm1 = -1e30f;
#pragma unroll
        for (int fj = 0; fj < 4; fj++) {
            lm0 = fmaxf(lm0, fmaxf(accs[fj][0], accs[fj][1]));
            lm1 = fmaxf(lm1, fmaxf(accs[fj][2], accs[fj][3]));
        }
        lm0 = fmaxf(lm0, __shfl_xor_sync(0xFFFFFFFF, lm0, 1));
        lm0 = fmaxf(lm0, __shfl_xor_sync(0xFFFFFFFF, lm0, 2));
        lm1 = fmaxf(lm1, __shfl_xor_sync(0xFFFFFFFF, lm1, 1));
        lm1 = fmaxf(lm1, __shfl_xor_sync(0xFFFFFFFF, lm1, 2));
        if ((lane & 3) == 0) {
            pmax[wn * 64 + r0] = lm0;
            pmax[wn * 64 + r1] = lm1;
        }
        __syncthreads();

        if (tid < 64) {
            float mo = mrow[tid];
            float mn = fmaxf(mo, fmaxf(pmax[tid], pmax[64 + tid]));
            mnew[tid] = mn;
            arow[tid] = __expf(mo - mn);
            mrow[tid] = mn;
        }
        __syncthreads();

        // ---- exp, write P' (hi|lo|hi), partial sums, rescale O ----
        const float mn0 = mnew[r0], mn1 = mnew[r1];
        const float al0 = arow[r0], al1 = arow[r1];
        float s0 = 0.f, s1 = 0.f;
#pragma unroll
        for (int fj = 0; fj < 4; fj++) {
            int kc = wn * 32 + fj * 8 + ecol;
            float p00 = __expf(accs[fj][0] - mn0);
            float p01 = __expf(accs[fj][1] - mn0);
            float p10 = __expf(accs[fj][2] - mn1);
            float p11 = __expf(accs[fj][3] - mn1);
            s0 += p00 + p01;
            s1 += p10 + p11;
            __nv_bfloat16 h00 = __float2bfloat16(p00), h01 = __float2bfloat16(p01);
            __nv_bfloat16 h10 = __float2bfloat16(p10), h11 = __float2bfloat16(p11);
            __nv_bfloat162 hp0 = __nv_bfloat162(h00, h01);
            __nv_bfloat162 hp1 = __nv_bfloat162(h10, h11);
            __nv_bfloat162 lp0 = __nv_bfloat162(
                __float2bfloat16(p00 - __bfloat162float(h00)),
                __float2bfloat16(p01 - __bfloat162float(h01)));
            __nv_bfloat162 lp1 = __nv_bfloat162(
                __float2bfloat16(p10 - __bfloat162float(h10)),
                __float2bfloat16(p11 - __bfloat162float(h11)));
            char* pr0 = sm + SP_OFF + r0 * APITCHB;
            char* pr1 = sm + SP_OFF + r1 * APITCHB;
            *(__nv_bfloat162*)(pr0 + kc * 2)       = hp0;
            *(__nv_bfloat162*)(pr0 + 128 + kc * 2) = lp0;
            *(__nv_bfloat162*)(pr0 + 256 + kc * 2) = hp0;
            *(__nv_bfloat162*)(pr1 + kc * 2)       = hp1;
            *(__nv_bfloat162*)(pr1 + 128 + kc * 2) = lp1;
            *(__nv_bfloat162*)(pr1 + 256 + kc * 2) = hp1;
        }
        s0 += __shfl_xor_sync(0xFFFFFFFF, s0, 1);
        s0 += __shfl_xor_sync(0xFFFFFFFF, s0, 2);
        s1 += __shfl_xor_sync(0xFFFFFFFF, s1, 1);
        s1 += __shfl_xor_sync(0xFFFFFFFF, s1, 2);
        if ((lane & 3) == 0) {
            psum[wn * 64 + r0] = s0;
            psum[wn * 64 + r1] = s1;
        }
#pragma unroll
        for (int fj = 0; fj < 4; fj++) {
            acco[fj][0] *= al0; acco[fj][1] *= al0;
            acco[fj][2] *= al1; acco[fj][3] *= al1;
        }
        __syncthreads();
        if (tid < 64)
            lrow[tid] = lrow[tid] * arow[tid] + psum[tid] + psum[64 + tid];

        // ---- O += P' VT'^T  (12 k-steps) ----
#pragma unroll
        for (int ks_ = 0; ks_ < 12; ks_++) {
            uint32_t af[4], bf[4][2];
            ldmx4(af, sb + SP_OFF + (wm * 16 + a_moff) * APITCHB + ks_ * 32 + a_half * 16);
#pragma unroll
            for (int jj = 0; jj < 2; jj++) {
                uint32_t r[4];
                ldmx4(r, sb + SV_OFF + (wn * 32 + jj * 16 + b_noff) * APITCHB
                         + ks_ * 32 + b_half * 16);
                bf[jj * 2][0] = r[0]; bf[jj * 2][1] = r[1];
                bf[jj * 2 + 1][0] = r[2]; bf[jj * 2 + 1][1] = r[3];
            }
#pragma unroll
            for (int fj = 0; fj < 4; fj++) mma16816(acco[fj], af, bf[fj]);
        }
        __syncthreads();
    }

    // ---- finalize: O /= l, stage split [hi|lo|hi] in SP region, then
    //      write coalesced 128B-line chunks into g_asplit ----
    const int b = bh >> 4, h = bh & 15;
    const float il0 = 1.f / lrow[r0];
    const float il1 = 1.f / lrow[r1];
#pragma unroll
    for (int fj = 0; fj < 4; fj++) {
        int d = wn * 32 + fj * 8 + ecol;       // 0..63 within head
        float f00 = acco[fj][0] * il0, f01 = acco[fj][1] * il0;
        float f10 = acco[fj][2] * il1, f11 = acco[fj][3] * il1;
        __nv_bfloat16 h00 = __float2bfloat16(f00), h01 = __float2bfloat16(f01);
        __nv_bfloat16 h10 = __float2bfloat16(f10), h11 = __float2bfloat16(f11);
        __nv_bfloat162 hp0 = __nv_bfloat162(h00, h01);
        __nv_bfloat162 hp1 = __nv_bfloat162(h10, h11);
        __nv_bfloat162 lp0 = __nv_bfloat162(
            __float2bfloat16(f00 - __bfloat162float(h00)),
            __float2bfloat16(f01 - __bfloat162float(h01)));
        __nv_bfloat162 lp1 = __nv_bfloat162(
            __float2bfloat16(f10 - __bfloat162float(h10)),
            __float2bfloat16(f11 - __bfloat162float(h11)));
        char* pr0 = sm + SP_OFF + r0 * APITCHB;
        char* pr1 = sm + SP_OFF + r1 * APITCHB;
        *(__nv_bfloat162*)(pr0 + d * 2)       = hp0;
        *(__nv_bfloat162*)(pr0 + 128 + d * 2) = lp0;
        *(__nv_bfloat162*)(pr0 + 256 + d * 2) = hp0;
        *(__nv_bfloat162*)(pr1 + d * 2)       = hp1;
        *(__nv_bfloat162*)(pr1 + 128 + d * 2) = lp1;
        *(__nv_bfloat162*)(pr1 + 256 + d * 2) = hp1;
    }
    __syncthreads();
    // write out: 64 rows x 3 segs x 128B
    {
        const size_t rowbase = (size_t)(b * SEQ + qb * 64);
#pragma unroll
        for (int it = 0; it < 6; it++) {
            int u = tid + it * 256;            // 0..1535
            int r = u / 24, w = u % 24;
            int seg = w >> 3, c = w & 7;
            uint4 v = *(uint4*)(sm + SP_OFF + r * APITCHB + seg * 128 + c * 16);
            *(uint4*)(outs + (rowbase + r) * K2 + seg * 1024 + h * 64 + c * 8) = v;
        }
    }
}

// ---------------------------------------------------------------------------
// Launch
// ---------------------------------------------------------------------------
extern "C" void kernel_launch(void* const* d_in, const int* in_sizes, int n_in,
                              void* d_out, int out_size)
{
    const float* Q   = (const float*)d_in[0];
    const float* K   = (const float*)d_in[1];
    const float* V   = (const float*)d_in[2];
    const float* W_Q = (const float*)d_in[4];
    const float* W_K = (const float*)d_in[5];
    const float* W_V = (const float*)d_in[6];
    const float* W_O = (const float*)d_in[7];
    float* out = (float*)d_out;

    float *pv;
    __nv_bfloat16 *pas, *pws, *pqs, *pks, *pvh, *pvl;
    cudaGetSymbolAddress((void**)&pv, g_v);
    cudaGetSymbolAddress((void**)&pas, g_asplit);
    cudaGetSymbolAddress((void**)&pws, g_wsplit);
    cudaGetSymbolAddress((void**)&pqs, g_qs);
    cudaGetSymbolAddress((void**)&pks, g_ks);
    cudaGetSymbolAddress((void**)&pvh, g_vth);
    cudaGetSymbolAddress((void**)&pvl, g_vtl);

    cudaFuncSetAttribute(gemm_mma,
                         cudaFuncAttributeMaxDynamicSharedMemorySize, GEMM_SMEM);
    cudaFuncSetAttribute(attn_mma,
                         cudaFuncAttributeMaxDynamicSharedMemorySize, ATTN_SMEM);

    const int actBlocks = ROWS * DMODEL / 4 / 256;     // 4096
    const int wgtBlocks = DMODEL * DMODEL / 4 / 256;   // 1024
    dim3 gg(DMODEL / GN, ROWS / GM);                   // (4, 32)

    // Q projection -> split attention layout directly (staged epilogue)
    split_kernel<<<actBlocks, 256>>>((const float4*)Q, pas, 1);
    split_kernel<<<wgtBlocks, 256>>>((const float4*)W_Q, pws, 0);
    gemm_mma<<<gg, 512, GEMM_SMEM>>>(pas, pws, nullptr, pqs, 1);
    // K projection -> split attention layout directly (staged epilogue)
    split_kernel<<<actBlocks, 256>>>((const float4*)K, pas, 1);
    split_kernel<<<wgtBlocks, 256>>>((const float4*)W_K, pws, 0);
    gemm_mma<<<gg, 512, GEMM_SMEM>>>(pas, pws, nullptr, pks, 2);
    // V projection -> fp32, then transpose+split
    split_kernel<<<actBlocks, 256>>>((const float4*)V, pas, 1);
    split_kernel<<<wgtBlocks, 256>>>((const float4*)W_V, pws, 0);
    gemm_mma<<<gg, 512, GEMM_SMEM>>>(pas, pws, pv, nullptr, 0);
    vt_split<<<dim3(32, 32), 256>>>(pv, pvh, pvl);

    // Tensor-core attention -> writes O-proj activations (split) directly
    attn_mma<<<dim3(SEQ / 64, BATCH * HEADS), 256, ATTN_SMEM>>>(pqs, pks, pvh, pvl, pas);

    // Output projection
    split_kernel<<<wgtBlocks, 256>>>((const float4*)W_O, pws, 0);
    gemm_mma<<<gg, 512, GEMM_SMEM>>>(pas, pws, out, nullptr, 0);
}